// round 10
// baseline (speedup 1.0000x reference)
#include <cuda_runtime.h>
#include <cuda_fp16.h>

#define N_VN    24576
#define D_V     4
#define D_C     8
#define E_EDGES (N_VN * D_V)     // 98304
#define M_CN    (E_EDGES / D_C)  // 12288
#define BSZ     64
#define CLIPV   20.0f
#define EPSV    1e-12f
#define S15     3.0517578125e-05f   // 2^-15
#define S14     6.103515625e-05f    // 2^-14

#define PLANEU1 (N_VN * 32)      // uint (=half2) elements per plane
#define BUFU1   (4 * PLANEU1)    // uint elements per buffer (4 slots)

#define CN_THREADS 131072        // 512 blocks x 256
#define WPT 3                    // work units per thread (exact: 3*131072 = M_CN*32)

// ---------------- scratch (device globals: allocation-free) ----------------
__device__ float    g_llrT[N_VN * BSZ];       // llr transposed [vn][b]
__device__ unsigned g_c2v[2 * BUFU1];         // double-buffered [buf][slot][vn][b/2]
__device__ int      g_vn_edges[N_VN * D_V];   // vn -> its 4 edges (sorted)
__device__ int2     g_eidx[E_EDGES];          // edge -> {vn*32, slot*PLANEU1+vn*32}
__device__ int      g_vn_cnt[N_VN];

__device__ __forceinline__ float clipf(float v, float lo, float hi) {
    return fminf(fmaxf(v, lo), hi);
}
__device__ __forceinline__ __half2 h2(unsigned u) {
    return *reinterpret_cast<__half2*>(&u);
}
__device__ __forceinline__ float copysgn(float mag, float s) {
    return __int_as_float((__float_as_int(mag) & 0x7fffffff) |
                          (__float_as_int(s) & 0x80000000));
}

// ------------- setup: transpose llr + zero cnt + zero c2v buf0 -------------
__global__ void k_setup(const float* __restrict__ in) {
    __shared__ float tile[BSZ * 33];
    int n0 = blockIdx.x * 32;
    int t = threadIdx.x;
#pragma unroll
    for (int k = 0; k < 8; k++) {       // load 32n x 64b tile (b-major source)
        int idx = t + k * 256;
        int nn = idx & 31, b = idx >> 5;
        tile[b * 33 + nn] = in[b * N_VN + n0 + nn];
    }
    if (t < 32) g_vn_cnt[n0 + t] = 0;
    {   // zero buffer 0 of c2v: 1024 uint4 per block x 768 blocks
        uint4* c4 = reinterpret_cast<uint4*>(g_c2v);
        int base = blockIdx.x * 1024;
#pragma unroll
        for (int k = 0; k < 4; k++)
            c4[base + t + k * 256] = make_uint4(0u, 0u, 0u, 0u);
    }
    __syncthreads();
#pragma unroll
    for (int k = 0; k < 8; k++) {
        int idx = t + k * 256;
        int b = idx & 63, nn = idx >> 6;
        g_llrT[(n0 + nn) * BSZ + b] = tile[b * 33 + nn];
    }
}

__global__ void k_build_inverse(const int* __restrict__ e2v) {
    int e = blockIdx.x * blockDim.x + threadIdx.x;
    if (e < E_EDGES) {
        int n = e2v[e];
        int pos = atomicAdd(&g_vn_cnt[n], 1);
        g_vn_edges[n * D_V + pos] = e;
    }
}

// sort each VN's 4 edges ascending (deterministic slots); emit index table
__global__ void k_sort4() {
    int n = blockIdx.x * blockDim.x + threadIdx.x;
    if (n >= N_VN) return;
    int* p = &g_vn_edges[n * 4];
    int a = p[0], b = p[1], c = p[2], d = p[3], x;
    if (a > b) { x = a; a = b; b = x; }
    if (c > d) { x = c; c = d; d = x; }
    if (a > c) { x = a; a = c; c = x; }
    if (b > d) { x = b; b = d; d = x; }
    if (b > c) { x = b; b = c; c = x; }
    p[0] = a; p[1] = b; p[2] = c; p[3] = d;
    int ro = n * 32;
    g_eidx[a] = make_int2(ro, 0 * PLANEU1 + ro);
    g_eidx[b] = make_int2(ro, 1 * PLANEU1 + ro);
    g_eidx[c] = make_int2(ro, 2 * PLANEU1 + ro);
    g_eidx[d] = make_int2(ro, 3 * PLANEU1 + ro);
}

// ------------- fused per-iteration kernel: belief-on-the-fly CN ------------
// One thread = one CN x 2 batch lanes, x3 sequential work units (single wave).
// Division-free extrinsic products: t = a/b with a=(e-1)*2^-15, b=(e+1)*2^-15;
// o_j = prefA*sufA * b_j * (1/B_tot)  -- one RCP per lane covers all 8 edges.
__global__ void __launch_bounds__(256, 4) k_cn(const float* __restrict__ cn_w,
                                               const float* __restrict__ ch_w,
                                               int it, int rb) {
    int tid = blockIdx.x * blockDim.x + threadIdx.x;
    float cw  = __ldg(&cn_w[it]);
    float chw = __ldg(&ch_w[it]);
    // saturated output value, computed with the reference's exact fp32 formula
    const float oc = 0.999999f;
    float satv = __logf(__fdividef(1.0f + oc, (1.0f - oc) + EPSV));
    const unsigned* rp = g_c2v + rb * BUFU1;
    unsigned*       wp = g_c2v + (rb ^ 1) * BUFU1;
    const float2* llr2 = reinterpret_cast<const float2*>(g_llrT);

#pragma unroll 1
    for (int u = 0; u < WPT; u++) {
        int widx = tid + u * CN_THREADS;
        int cn = widx >> 5, qq = widx & 31;
        int ebase = cn * D_C;

        float aX[D_C], aY[D_C], sX[D_C], sY[D_C];
        int wof[D_C];
        float BX = 1.0f, BY = 1.0f;
#pragma unroll
        for (int j = 0; j < D_C; j++) {
            int2 ix = __ldg(&g_eidx[ebase + j]);   // uniform within warp
            int ro = ix.x + qq;
            wof[j] = ix.y + qq;
            unsigned u0 = rp[ro];
            unsigned u1 = rp[ro + PLANEU1];
            unsigned u2 = rp[ro + 2 * PLANEU1];
            unsigned u3 = rp[ro + 3 * PLANEU1];
            unsigned uo = rp[wof[j]];              // own c2v
            __half2 sA = __hadd2(__hadd2(h2(u0), h2(u1)), __hadd2(h2(u2), h2(u3)));
            float2 sa = __half22float2(sA);
            float2 oa = __half22float2(h2(uo));
            float2 L = llr2[ro];
            float vx = clipf(fmaf(L.x, chw, sa.x) - oa.x, -CLIPV, CLIPV);
            float vy = clipf(fmaf(L.y, chw, sa.y) - oa.y, -CLIPV, CLIPV);
            float ex = __expf(vx);
            float ey = __expf(vy);
            float ax = fmaf(ex, S15, -S15);        // (e-1)*2^-15
            float ay = fmaf(ey, S15, -S15);
            float bx = fmaf(ex, S15,  S15);        // (e+1)*2^-15
            float by = fmaf(ey, S15,  S15);
            aX[j] = ax; aY[j] = ay;
            BX *= bx;   BY *= by;
        }
        float rBX = __fdividef(1.0f, BX);
        float rBY = __fdividef(1.0f, BY);

        // suffix products of a
        float SX = 1.0f, SY = 1.0f;
#pragma unroll
        for (int j = D_C - 1; j >= 0; j--) {
            sX[j] = SX; SX *= aX[j];
            sY[j] = SY; SY *= aY[j];
        }

        // output pass: prefix running, o = P*suf*b*rB
        float PX = 1.0f, PY = 1.0f;
#pragma unroll
        for (int j = 0; j < D_C; j++) {
            float bx = aX[j] + S14;                // b = a + 2^-14 (exact reln)
            float by = aY[j] + S14;
            float ox = PX * sX[j] * bx * rBX;
            float oy = PY * sY[j] * by * rBY;
            float lgx = __logf(__fdividef(1.0f + ox, (1.0f - ox) + EPSV));
            float lgy = __logf(__fdividef(1.0f + oy, (1.0f - oy) + EPSV));
            float ux = (fabsf(ox) > oc) ? copysgn(satv, ox) : lgx;
            float uy = (fabsf(oy) > oc) ? copysgn(satv, oy) : lgy;
            float cx = clipf(ux * cw, -CLIPV, CLIPV);
            float cy = clipf(uy * cw, -CLIPV, CLIPV);
            __half2 h = __floats2half2_rn(cx, cy);
            wp[wof[j]] = *reinterpret_cast<unsigned*>(&h);
            PX *= aX[j];
            PY *= aY[j];
        }
    }
}

// ---------------- final: dec = llr_in + sum c2v, transposed out ------------
__global__ void k_out(const float* __restrict__ in, float* __restrict__ out,
                      int fb) {
    __shared__ float tile[BSZ * 33];
    const __half* cv = reinterpret_cast<const __half*>(g_c2v + fb * BUFU1);
    int n0 = blockIdx.x * 32;
    int t = threadIdx.x;
#pragma unroll
    for (int k = 0; k < 8; k++) {       // b-fast mapping: coalesced plane reads
        int idx = t + k * 256;
        int b = idx & 63, nn = idx >> 6;
        int n = n0 + nn;
        float s = ((__half2float(cv[0 * N_VN * BSZ + n * BSZ + b]) +
                    __half2float(cv[1 * N_VN * BSZ + n * BSZ + b])) +
                    __half2float(cv[2 * N_VN * BSZ + n * BSZ + b])) +
                    __half2float(cv[3 * N_VN * BSZ + n * BSZ + b]);
        tile[b * 33 + nn] = s;
    }
    __syncthreads();
#pragma unroll
    for (int k = 0; k < 8; k++) {       // n-fast mapping: coalesced out writes
        int idx = t + k * 256;
        int nn = idx & 31, b = idx >> 5;
        out[b * N_VN + n0 + nn] = in[b * N_VN + n0 + nn] + tile[b * 33 + nn];
    }
}

// ---------------- launch ----------------
extern "C" void kernel_launch(void* const* d_in, const int* in_sizes, int n_in,
                              void* d_out, int out_size) {
    const float* llr  = (const float*)d_in[0];
    const float* cn_w = (const float*)d_in[1];
    const float* ch_w = (const float*)d_in[2];
    const int*   e2v  = (const int*)d_in[3];
    int iters = in_sizes[1];   // cn_weight length

    k_setup<<<N_VN / 32, 256>>>(llr);
    k_build_inverse<<<(E_EDGES + 255) / 256, 256>>>(e2v);
    k_sort4<<<(N_VN + 255) / 256, 256>>>();

    for (int it = 0; it < iters; it++)
        k_cn<<<CN_THREADS / 256, 256>>>(cn_w, ch_w, it, it & 1);

    k_out<<<N_VN / 32, 256>>>(llr, (float*)d_out, iters & 1);
}

// round 11
// speedup vs baseline: 1.1375x; 1.1375x over previous
#include <cuda_runtime.h>
#include <cuda_fp16.h>

#define N_VN    24576
#define D_V     4
#define D_C     8
#define E_EDGES (N_VN * D_V)     // 98304
#define M_CN    (E_EDGES / D_C)  // 12288
#define BSZ     64
#define CLIPV   20.0f
#define EPSV    1e-12f
#define S15     3.0517578125e-05f   // 2^-15
#define S14     6.103515625e-05f    // 2^-14
#define LN2F    0.69314718056f

#define PLANEU2 (N_VN * 16)      // uint2 (=4 halves) elements per plane
#define BUFU2   (4 * PLANEU2)    // uint2 elements per buffer (4 slots)

// ---------------- scratch (device globals: allocation-free) ----------------
__device__ float g_llrT[N_VN * BSZ];               // llr transposed [vn][b]
__device__ uint2 g_c2v[2 * BUFU2];                 // double-buffered [buf][slot][vn][b/4]
__device__ int   g_vn_edges[N_VN * D_V];           // vn -> its 4 edges (sorted)
__device__ __align__(16) int2 g_eidx[E_EDGES];     // edge -> {vn*16, slot*PLANEU2+vn*16}
__device__ int   g_vn_cnt[N_VN];

__device__ __forceinline__ float clipf(float v, float lo, float hi) {
    return fminf(fmaxf(v, lo), hi);
}
__device__ __forceinline__ __half2 h2(unsigned u) {
    return *reinterpret_cast<__half2*>(&u);
}
__device__ __forceinline__ float copysgn(float mag, float s) {
    return __int_as_float((__float_as_int(mag) & 0x7fffffff) |
                          (__float_as_int(s) & 0x80000000));
}

// ------------- setup: transpose llr + zero cnt + zero c2v buf0 -------------
__global__ void k_setup(const float* __restrict__ in) {
    __shared__ float tile[BSZ * 33];
    int n0 = blockIdx.x * 32;
    int t = threadIdx.x;
#pragma unroll
    for (int k = 0; k < 8; k++) {       // load 32n x 64b tile (b-major source)
        int idx = t + k * 256;
        int nn = idx & 31, b = idx >> 5;
        tile[b * 33 + nn] = in[b * N_VN + n0 + nn];
    }
    if (t < 32) g_vn_cnt[n0 + t] = 0;
    {   // zero buffer 0 of c2v: 1024 uint4 per block x 768 blocks
        uint4* c4 = reinterpret_cast<uint4*>(g_c2v);
        int base = blockIdx.x * 1024;
#pragma unroll
        for (int k = 0; k < 4; k++)
            c4[base + t + k * 256] = make_uint4(0u, 0u, 0u, 0u);
    }
    __syncthreads();
#pragma unroll
    for (int k = 0; k < 8; k++) {
        int idx = t + k * 256;
        int b = idx & 63, nn = idx >> 6;
        g_llrT[(n0 + nn) * BSZ + b] = tile[b * 33 + nn];
    }
}

__global__ void k_build_inverse(const int* __restrict__ e2v) {
    int e = blockIdx.x * blockDim.x + threadIdx.x;
    if (e < E_EDGES) {
        int n = e2v[e];
        int pos = atomicAdd(&g_vn_cnt[n], 1);
        g_vn_edges[n * D_V + pos] = e;
    }
}

// sort each VN's 4 edges ascending (deterministic slots); emit index table
__global__ void k_sort4() {
    int n = blockIdx.x * blockDim.x + threadIdx.x;
    if (n >= N_VN) return;
    int* p = &g_vn_edges[n * 4];
    int a = p[0], b = p[1], c = p[2], d = p[3], x;
    if (a > b) { x = a; a = b; b = x; }
    if (c > d) { x = c; c = d; d = x; }
    if (a > c) { x = a; a = c; c = x; }
    if (b > d) { x = b; b = d; d = x; }
    if (b > c) { x = b; b = c; c = x; }
    p[0] = a; p[1] = b; p[2] = c; p[3] = d;
    int ro = n * 16;
    g_eidx[a] = make_int2(ro, 0 * PLANEU2 + ro);
    g_eidx[b] = make_int2(ro, 1 * PLANEU2 + ro);
    g_eidx[c] = make_int2(ro, 2 * PLANEU2 + ro);
    g_eidx[d] = make_int2(ro, 3 * PLANEU2 + ro);
}

// ------------- fused per-iteration kernel: belief-on-the-fly CN ------------
// One thread = one CN x 4 batch lanes (16 threads per CN). Reads buffer rb,
// writes buffer rb^1 (double buffer). Division-free CN math:
//   a=(e^v-1)*2^-15, b=(e^v+1)*2^-15, B=prod b, C_j=prefA*sufA*b_j
//   u_j = (log2(B+C_j) - log2(B-C_j)) * ln2        (no divisions at all)
// MUFU per edge-lane: EX2 + 2*LG2 = 3 (was 4).
__global__ void __launch_bounds__(256, 2) k_cn(const float* __restrict__ cn_w,
                                               const float* __restrict__ ch_w,
                                               int it, int rb) {
    int idx = blockIdx.x * blockDim.x + threadIdx.x;   // M_CN * 16
    int cn = idx >> 4, qq = idx & 15;
    float cw  = __ldg(&cn_w[it]);
    float chw = __ldg(&ch_w[it]);
    const float oc = 0.999999f;
    // saturated value in log2 domain (reference's exact fp32 formula / ln2)
    float satl2 = __log2f(__fdividef(1.0f + oc, (1.0f - oc) + EPSV));
    float cwl2  = cw * LN2F;
    const uint2* rp = g_c2v + rb * BUFU2;
    uint2*       wp = g_c2v + (rb ^ 1) * BUFU2;
    const float4* llr4 = reinterpret_cast<const float4*>(g_llrT);

    // prefetch all 8 edge index pairs (4x LDG.128) -> flat load chain
    const int4* ei4 = reinterpret_cast<const int4*>(g_eidx + cn * D_C);
    int4 e01 = __ldg(ei4 + 0);
    int4 e23 = __ldg(ei4 + 1);
    int4 e45 = __ldg(ei4 + 2);
    int4 e67 = __ldg(ei4 + 3);
    int ros[D_C] = {e01.x, e01.z, e23.x, e23.z, e45.x, e45.z, e67.x, e67.z};
    int wfs[D_C] = {e01.y, e01.w, e23.y, e23.w, e45.y, e45.w, e67.y, e67.w};

    float4 a[D_C], s[D_C];
    float4 B = make_float4(1.f, 1.f, 1.f, 1.f);
#pragma unroll
    for (int j = 0; j < D_C; j++) {
        int ro = ros[j] + qq;
        int wf = wfs[j] + qq;
        wfs[j] = wf;
        uint2 u0 = rp[ro];
        uint2 u1 = rp[ro + PLANEU2];
        uint2 u2 = rp[ro + 2 * PLANEU2];
        uint2 u3 = rp[ro + 3 * PLANEU2];
        uint2 uo = rp[wf];                         // own c2v (no slot selects)
        __half2 sA = __hadd2(__hadd2(h2(u0.x), h2(u1.x)), __hadd2(h2(u2.x), h2(u3.x)));
        __half2 sB = __hadd2(__hadd2(h2(u0.y), h2(u1.y)), __hadd2(h2(u2.y), h2(u3.y)));
        float2 sa = __half22float2(sA), sb = __half22float2(sB);
        float2 oa = __half22float2(h2(uo.x)), ob = __half22float2(h2(uo.y));
        float4 L = llr4[ro];
        float vx = clipf(fmaf(L.x, chw, sa.x) - oa.x, -CLIPV, CLIPV);
        float vy = clipf(fmaf(L.y, chw, sa.y) - oa.y, -CLIPV, CLIPV);
        float vz = clipf(fmaf(L.z, chw, sb.x) - ob.x, -CLIPV, CLIPV);
        float vw = clipf(fmaf(L.w, chw, sb.y) - ob.y, -CLIPV, CLIPV);
        float ex = __expf(vx), ey = __expf(vy), ez = __expf(vz), ew = __expf(vw);
        a[j].x = fmaf(ex, S15, -S15);
        a[j].y = fmaf(ey, S15, -S15);
        a[j].z = fmaf(ez, S15, -S15);
        a[j].w = fmaf(ew, S15, -S15);
        B.x *= fmaf(ex, S15, S15);
        B.y *= fmaf(ey, S15, S15);
        B.z *= fmaf(ez, S15, S15);
        B.w *= fmaf(ew, S15, S15);
    }
    float4 ocB;
    ocB.x = oc * B.x; ocB.y = oc * B.y; ocB.z = oc * B.z; ocB.w = oc * B.w;

    // suffix products of a
    float4 S = make_float4(1.f, 1.f, 1.f, 1.f);
#pragma unroll
    for (int j = D_C - 1; j >= 0; j--) {
        s[j] = S;
        S.x *= a[j].x; S.y *= a[j].y; S.z *= a[j].z; S.w *= a[j].w;
    }

    // output pass: running prefix P, C = P*suf*b, u from two log2s
    float4 P = make_float4(1.f, 1.f, 1.f, 1.f);
#pragma unroll
    for (int j = 0; j < D_C; j++) {
        float bx = a[j].x + S14, by = a[j].y + S14;
        float bz = a[j].z + S14, bw = a[j].w + S14;
        float Cx = (P.x * s[j].x) * bx;
        float Cy = (P.y * s[j].y) * by;
        float Cz = (P.z * s[j].z) * bz;
        float Cw = (P.w * s[j].w) * bw;
        float dx = __log2f(B.x + Cx) - __log2f(B.x - Cx);
        float dy = __log2f(B.y + Cy) - __log2f(B.y - Cy);
        float dz = __log2f(B.z + Cz) - __log2f(B.z - Cz);
        float dw = __log2f(B.w + Cw) - __log2f(B.w - Cw);
        dx = (fabsf(Cx) > ocB.x) ? copysgn(satl2, Cx) : dx;
        dy = (fabsf(Cy) > ocB.y) ? copysgn(satl2, Cy) : dy;
        dz = (fabsf(Cz) > ocB.z) ? copysgn(satl2, Cz) : dz;
        dw = (fabsf(Cw) > ocB.w) ? copysgn(satl2, Cw) : dw;
        float cx = clipf(dx * cwl2, -CLIPV, CLIPV);
        float cy = clipf(dy * cwl2, -CLIPV, CLIPV);
        float cz = clipf(dz * cwl2, -CLIPV, CLIPV);
        float cwv = clipf(dw * cwl2, -CLIPV, CLIPV);
        __half2 ha = __floats2half2_rn(cx, cy);
        __half2 hb = __floats2half2_rn(cz, cwv);
        uint2 o;
        o.x = *reinterpret_cast<unsigned*>(&ha);
        o.y = *reinterpret_cast<unsigned*>(&hb);
        wp[wfs[j]] = o;
        P.x *= a[j].x; P.y *= a[j].y; P.z *= a[j].z; P.w *= a[j].w;
    }
}

// ---------------- final: dec = llr_in + sum c2v, transposed out ------------
__global__ void k_out(const float* __restrict__ in, float* __restrict__ out,
                      int fb) {
    __shared__ float tile[BSZ * 33];
    const __half* cv = reinterpret_cast<const __half*>(g_c2v + fb * BUFU2);
    int n0 = blockIdx.x * 32;
    int t = threadIdx.x;
#pragma unroll
    for (int k = 0; k < 8; k++) {       // b-fast mapping: coalesced plane reads
        int idx = t + k * 256;
        int b = idx & 63, nn = idx >> 6;
        int n = n0 + nn;
        float s = ((__half2float(cv[0 * N_VN * BSZ + n * BSZ + b]) +
                    __half2float(cv[1 * N_VN * BSZ + n * BSZ + b])) +
                    __half2float(cv[2 * N_VN * BSZ + n * BSZ + b])) +
                    __half2float(cv[3 * N_VN * BSZ + n * BSZ + b]);
        tile[b * 33 + nn] = s;
    }
    __syncthreads();
#pragma unroll
    for (int k = 0; k < 8; k++) {       // n-fast mapping: coalesced out writes
        int idx = t + k * 256;
        int nn = idx & 31, b = idx >> 5;
        out[b * N_VN + n0 + nn] = in[b * N_VN + n0 + nn] + tile[b * 33 + nn];
    }
}

// ---------------- launch ----------------
extern "C" void kernel_launch(void* const* d_in, const int* in_sizes, int n_in,
                              void* d_out, int out_size) {
    const float* llr  = (const float*)d_in[0];
    const float* cn_w = (const float*)d_in[1];
    const float* ch_w = (const float*)d_in[2];
    const int*   e2v  = (const int*)d_in[3];
    int iters = in_sizes[1];   // cn_weight length

    k_setup<<<N_VN / 32, 256>>>(llr);
    k_build_inverse<<<(E_EDGES + 255) / 256, 256>>>(e2v);
    k_sort4<<<(N_VN + 255) / 256, 256>>>();

    for (int it = 0; it < iters; it++)
        k_cn<<<(M_CN * 16) / 256, 256>>>(cn_w, ch_w, it, it & 1);

    k_out<<<N_VN / 32, 256>>>(llr, (float*)d_out, iters & 1);
}